// round 6
// baseline (speedup 1.0000x reference)
#include <cuda_runtime.h>
#include <cuda_bf16.h>
#include <cstdint>

// Problem constants (fixed by the reference)
#define B_ 8
#define S_ 8192
#define H_ 512
#define D_ 768
#define P_ 128

#define K2_ (H_ / 2)   // 256 packed bf16x2 words per row

// Scratch (no allocations allowed): A pre-split into bf16 hi/lo, packed pairs
// (k even in low 16 bits, k odd in high 16 bits)
__device__ uint32_t g_Ah[B_ * P_ * K2_];
__device__ uint32_t g_Al[B_ * P_ * K2_];

__device__ __forceinline__ uint32_t bf16pack(float even_elem, float odd_elem) {
    uint32_t r;   // low 16 = even k, high 16 = odd k
    asm("cvt.rn.bf16x2.f32 %0, %1, %2;" : "=r"(r) : "f"(odd_elem), "f"(even_elem));
    return r;
}

__device__ __forceinline__ void bsplit(float v, float& h, float& l) {
    h = __bfloat162float(__float2bfloat16_rn(v));
    l = v - h;
}

// ---------------------------------------------------------------------------
// Kernel 1: segment mean via binary search; writes pre-split packed bf16 A.
// grid = (P_, B_, 2) ; block = 64 threads, each owns one float4 h-column.
// ---------------------------------------------------------------------------
__global__ void pool_kernel(const float* __restrict__ x,
                            const int*   __restrict__ pids) {
    const int b  = blockIdx.y;
    const int p  = blockIdx.x;
    const int hq = blockIdx.z * 64 + threadIdx.x;   // float4 column 0..127

    const int* row = pids + (size_t)b * S_;

    int lo = 0, hi = S_;
    while (lo < hi) {
        int mid = (lo + hi) >> 1;
        if (__ldg(row + mid) < p) lo = mid + 1; else hi = mid;
    }
    const int s0 = lo;
    hi = S_;
    while (lo < hi) {
        int mid = (lo + hi) >> 1;
        if (__ldg(row + mid) < p + 1) lo = mid + 1; else hi = mid;
    }
    const int s1 = lo;

    const float4* xp = (const float4*)x + (size_t)b * S_ * (H_ / 4) + hq;

    float4 a[8];
#pragma unroll
    for (int i = 0; i < 8; ++i) a[i] = make_float4(0.f, 0.f, 0.f, 0.f);

    int s = s0;
    for (; s + 8 <= s1; s += 8) {
#pragma unroll
        for (int i = 0; i < 8; ++i) {
            const float4 v = __ldcs(&xp[(size_t)(s + i) * (H_ / 4)]);
            a[i].x += v.x; a[i].y += v.y; a[i].z += v.z; a[i].w += v.w;
        }
    }
    for (; s < s1; ++s) {
        const float4 v = __ldcs(&xp[(size_t)s * (H_ / 4)]);
        a[0].x += v.x; a[0].y += v.y; a[0].z += v.z; a[0].w += v.w;
    }

#pragma unroll
    for (int i = 0; i < 4; ++i) {
        a[i].x += a[i + 4].x; a[i].y += a[i + 4].y;
        a[i].z += a[i + 4].z; a[i].w += a[i + 4].w;
    }
    a[0].x += a[2].x; a[0].y += a[2].y; a[0].z += a[2].z; a[0].w += a[2].w;
    a[1].x += a[3].x; a[1].y += a[3].y; a[1].z += a[3].z; a[1].w += a[3].w;

    const int   cnt = s1 - s0;
    const float rc  = cnt ? (1.0f / (float)cnt) : 0.0f;   // max(cnt,1) semantics
    const float m0v = (a[0].x + a[1].x) * rc;
    const float m1v = (a[0].y + a[1].y) * rc;
    const float m2v = (a[0].z + a[1].z) * rc;
    const float m3v = (a[0].w + a[1].w) * rc;

    float h0,l0,h1,l1,h2,l2,h3,l3;
    bsplit(m0v,h0,l0); bsplit(m1v,h1,l1);
    bsplit(m2v,h2,l2); bsplit(m3v,h3,l3);

    const size_t base = (size_t)(b * P_ + p) * K2_ + 2 * hq;
    uint2 vh, vl;
    vh.x = bf16pack(h0, h1); vh.y = bf16pack(h2, h3);
    vl.x = bf16pack(l0, l1); vl.y = bf16pack(l2, l3);
    *(uint2*)(g_Ah + base) = vh;
    *(uint2*)(g_Al + base) = vl;
}

// ---------------------------------------------------------------------------
// Kernel 2: out = A @ W + bias, bf16 3-product split (A pre-split by pool).
// M=1024, K=512, N=768. Block 64x96, BK=32, 512 threads (16 warps: 4m x 4n),
// warp tile 16x24 (1 mf x 3 nf), 2 k-slabs/iter, 16 iters.
// Double-buffered, register prefetch, one sync/iter. grid=(8,16)=128 blocks.
// ---------------------------------------------------------------------------
#define BM 64
#define BN 96
#define BK 32
#define BK2 (BK / 2)   // 16 packed words

__device__ __forceinline__ void mma_bf16(float* c, const uint32_t* a,
                                         uint32_t b0, uint32_t b1) {
    asm volatile(
        "mma.sync.aligned.m16n8k16.row.col.f32.bf16.bf16.f32 "
        "{%0,%1,%2,%3}, {%4,%5,%6,%7}, {%8,%9}, {%0,%1,%2,%3};"
        : "+f"(c[0]), "+f"(c[1]), "+f"(c[2]), "+f"(c[3])
        : "r"(a[0]), "r"(a[1]), "r"(a[2]), "r"(a[3]), "r"(b0), "r"(b1));
}

__global__ __launch_bounds__(512, 1)
void gemm_kernel(const float* __restrict__ W,
                 const float* __restrict__ bias,
                 float* __restrict__ out) {
    // A: [m][k2], k2 padded 16 -> 20 ; W: [k2][n], n padded 96 -> 104
    __shared__ uint32_t Ah[2][BM][20];
    __shared__ uint32_t Al[2][BM][20];
    __shared__ uint32_t Wh[2][BK2][104];
    __shared__ uint32_t Wl[2][BK2][104];

    const int m0 = blockIdx.y * BM;
    const int n0 = blockIdx.x * BN;
    const int t  = threadIdx.x;          // 0..511
    const int w  = t >> 5;               // warp 0..15
    const int ln = t & 31;
    const int g  = ln >> 2;              // groupID 0..7
    const int tg = ln & 3;               // threadID_in_group 0..3
    const int wm = w & 3;                // warp m (0..3) -> 16 rows
    const int wn = w >> 2;               // warp n (0..3) -> 24 cols

    // A loader: row lr (0..63), k2 pair lka (0,2,...,14) -> uint2
    const int lr  = t >> 3;
    const int lka = (t & 7) * 2;
    const uint32_t* Ahp = g_Ah + (size_t)(m0 + lr) * K2_ + lka;
    const uint32_t* Alp = g_Al + (size_t)(m0 + lr) * K2_ + lka;

    // W loader: k-pair k2w (0..15), col base nb (0,3,...,93): 2 rows x 3 cols
    const int k2w = t >> 5;
    const int nb  = (t & 31) * 3;
    const float* Wp0 = W + (size_t)(2 * k2w) * D_ + n0 + nb;   // even k row
    const float* Wp1 = Wp0 + D_;                               // odd k row

    float acc[3][4] = {};                // [nf][c0..c3]

    uint2  a2h, a2l;
    float  wv0[3], wv1[3];

    // ---- prologue: tile 0 -> buffer 0
    a2h = *(const uint2*)(Ahp);
    a2l = *(const uint2*)(Alp);
#pragma unroll
    for (int j = 0; j < 3; ++j) { wv0[j] = Wp0[j]; wv1[j] = Wp1[j]; }
    *(uint2*)&Ah[0][lr][lka] = a2h;
    *(uint2*)&Al[0][lr][lka] = a2l;
#pragma unroll
    for (int j = 0; j < 3; ++j) {
        float ha,la,hb,lb;
        bsplit(wv0[j], ha, la); bsplit(wv1[j], hb, lb);
        Wh[0][k2w][nb + j] = bf16pack(ha, hb);
        Wl[0][k2w][nb + j] = bf16pack(la, lb);
    }
    __syncthreads();

    int cur = 0;
    for (int k0 = BK; k0 <= H_; k0 += BK) {
        const bool more = (k0 < H_);
        if (more) {
            const int k2o = k0 / 2;
            a2h = *(const uint2*)(Ahp + k2o);
            a2l = *(const uint2*)(Alp + k2o);
            const float* p0 = Wp0 + (size_t)k0 * D_;
            const float* p1 = Wp1 + (size_t)k0 * D_;
#pragma unroll
            for (int j = 0; j < 3; ++j) { wv0[j] = p0[j]; wv1[j] = p1[j]; }
        }

        // ---- compute: 2 k-slabs of m16n8k16
#pragma unroll
        for (int ks = 0; ks < 2; ++ks) {
            const int r  = wm * 16 + g;
            const int c  = ks * 8 + tg;
            uint32_t ah[4], al[4];
            ah[0] = Ah[cur][r][c];         al[0] = Al[cur][r][c];
            ah[1] = Ah[cur][r + 8][c];     al[1] = Al[cur][r + 8][c];
            ah[2] = Ah[cur][r][c + 4];     al[2] = Al[cur][r][c + 4];
            ah[3] = Ah[cur][r + 8][c + 4]; al[3] = Al[cur][r + 8][c + 4];
#pragma unroll
            for (int nf = 0; nf < 3; ++nf) {
                const int n = wn * 24 + nf * 8 + g;
                const uint32_t bh0 = Wh[cur][c][n],     bh1 = Wh[cur][c + 4][n];
                const uint32_t bl0 = Wl[cur][c][n],     bl1 = Wl[cur][c + 4][n];
                mma_bf16(acc[nf], ah, bh0, bh1);   // hi*hi
                mma_bf16(acc[nf], al, bh0, bh1);   // lo*hi
                mma_bf16(acc[nf], ah, bl0, bl1);   // hi*lo
            }
        }

        if (more) {
            const int nxt = cur ^ 1;
            *(uint2*)&Ah[nxt][lr][lka] = a2h;
            *(uint2*)&Al[nxt][lr][lka] = a2l;
#pragma unroll
            for (int j = 0; j < 3; ++j) {
                float ha,la,hb,lb;
                bsplit(wv0[j], ha, la); bsplit(wv1[j], hb, lb);
                Wh[nxt][k2w][nb + j] = bf16pack(ha, hb);
                Wl[nxt][k2w][nb + j] = bf16pack(la, lb);
            }
            __syncthreads();
            cur = nxt;
        }
    }

    // ---- epilogue: c0,c1 = row g cols 2tg,2tg+1 ; c2,c3 = row g+8
#pragma unroll
    for (int nf = 0; nf < 3; ++nf) {
        const int ncol = n0 + wn * 24 + nf * 8 + 2 * tg;
        const float2 bv = *(const float2*)(bias + ncol);
        const int mrow = m0 + wm * 16 + g;
        float2 o0, o1;
        o0.x = acc[nf][0] + bv.x;  o0.y = acc[nf][1] + bv.y;
        o1.x = acc[nf][2] + bv.x;  o1.y = acc[nf][3] + bv.y;
        *(float2*)(out + (size_t)mrow * D_ + ncol)       = o0;
        *(float2*)(out + (size_t)(mrow + 8) * D_ + ncol) = o1;
    }
}

// ---------------------------------------------------------------------------
// Launch
// ---------------------------------------------------------------------------
extern "C" void kernel_launch(void* const* d_in, const int* in_sizes, int n_in,
                              void* d_out, int out_size) {
    const float* x    = (const float*)d_in[0];   // byte_hiddens [B,S,H]
    const float* W    = (const float*)d_in[1];   // W_proj [H,D]
    const float* bias = (const float*)d_in[2];   // b_proj [D]
    const int*   pids = (const int*)  d_in[3];   // patch_ids [B,S]
    float*       out  = (float*)d_out;           // [B,P,D]

    pool_kernel<<<dim3(P_, B_, 2), 64>>>(x, pids);
    gemm_kernel<<<dim3(D_ / BN, (B_ * P_) / BM), 512>>>(W, bias, out);
}

// round 8
// speedup vs baseline: 1.2205x; 1.2205x over previous
#include <cuda_runtime.h>
#include <cuda_bf16.h>
#include <cstdint>

// Problem constants (fixed by the reference)
#define B_ 8
#define S_ 8192
#define H_ 512
#define D_ 768
#define P_ 128
#define M_ (B_ * P_)     // 1024
#define K2_ (H_ / 2)     // 256 packed bf16x2 words per k-row

// Scratch (no allocations allowed), all packed bf16x2 (k even low, k odd high)
__device__ __align__(16) uint32_t g_Ah[M_ * K2_];    // A hi  [m][k2]
__device__ __align__(16) uint32_t g_Al[M_ * K2_];    // A lo  [m][k2]
__device__ __align__(16) uint32_t g_Wh[K2_ * D_];    // W hi  [k2][n]
__device__ __align__(16) uint32_t g_Wl[K2_ * D_];    // W lo  [k2][n]

__device__ __forceinline__ uint32_t bf16pack(float even_e, float odd_e) {
    uint32_t r;   // low 16 = even k, high 16 = odd k
    asm("cvt.rn.bf16x2.f32 %0, %1, %2;" : "=r"(r) : "f"(odd_e), "f"(even_e));
    return r;
}

__device__ __forceinline__ void bsplit(float v, float& h, float& l) {
    h = __bfloat162float(__float2bfloat16_rn(v));
    l = v - h;
}

// ---------------------------------------------------------------------------
// Kernel 1: segment mean (binary search over sorted patch_ids) -> packed
// bf16 hi/lo A planes. ALSO folds in the W split/pack (3 words per thread).
// grid = (P_, B_, 2), block = 32. Thread owns 8 consecutive k.
// ---------------------------------------------------------------------------
__global__ void pool_kernel(const float* __restrict__ x,
                            const float* __restrict__ W,
                            const int*   __restrict__ pids) {
    const int b = blockIdx.y;
    const int p = blockIdx.x;
    const int z = blockIdx.z;
    const int t = threadIdx.x;

    // ---- W split/pack: 65536 threads x 3 words = 196608 = K2_*D_
    const int gtid = ((z * B_ + b) * P_ + p) * 32 + t;
#pragma unroll
    for (int i = 0; i < 3; ++i) {
        const int idx = i * 65536 + gtid;
        const int k2  = idx / D_;
        const int n   = idx - k2 * D_;
        const float w0 = W[(size_t)(2 * k2) * D_ + n];
        const float w1 = W[(size_t)(2 * k2 + 1) * D_ + n];
        float h0, l0, h1, l1;
        bsplit(w0, h0, l0); bsplit(w1, h1, l1);
        g_Wh[idx] = bf16pack(h0, h1);
        g_Wl[idx] = bf16pack(l0, l1);
    }

    // ---- binary search for patch range
    const int* row = pids + (size_t)b * S_;
    int lo = 0, hi = S_;
    while (lo < hi) { int m = (lo + hi) >> 1; if (__ldg(row + m) < p) lo = m + 1; else hi = m; }
    const int s0 = lo;
    hi = S_;
    while (lo < hi) { int m = (lo + hi) >> 1; if (__ldg(row + m) < p + 1) lo = m + 1; else hi = m; }
    const int s1 = lo;

    // ---- stream & accumulate: thread owns k = 8*kq .. 8*kq+7
    const int kq = z * 32 + t;                       // 0..63
    const float4* xp = (const float4*)x + (size_t)b * S_ * (H_ / 4) + kq * 2;

    float4 a[4][2];
#pragma unroll
    for (int i = 0; i < 4; ++i) {
        a[i][0] = make_float4(0.f, 0.f, 0.f, 0.f);
        a[i][1] = make_float4(0.f, 0.f, 0.f, 0.f);
    }
    int s = s0;
    for (; s + 4 <= s1; s += 4) {
#pragma unroll
        for (int i = 0; i < 4; ++i) {
            const float4 v0 = __ldcs(&xp[(size_t)(s + i) * (H_ / 4)]);
            const float4 v1 = __ldcs(&xp[(size_t)(s + i) * (H_ / 4) + 1]);
            a[i][0].x += v0.x; a[i][0].y += v0.y; a[i][0].z += v0.z; a[i][0].w += v0.w;
            a[i][1].x += v1.x; a[i][1].y += v1.y; a[i][1].z += v1.z; a[i][1].w += v1.w;
        }
    }
    for (; s < s1; ++s) {
        const float4 v0 = __ldcs(&xp[(size_t)s * (H_ / 4)]);
        const float4 v1 = __ldcs(&xp[(size_t)s * (H_ / 4) + 1]);
        a[0][0].x += v0.x; a[0][0].y += v0.y; a[0][0].z += v0.z; a[0][0].w += v0.w;
        a[0][1].x += v1.x; a[0][1].y += v1.y; a[0][1].z += v1.z; a[0][1].w += v1.w;
    }
#pragma unroll
    for (int q = 0; q < 2; ++q) {
        a[0][q].x += a[2][q].x; a[0][q].y += a[2][q].y; a[0][q].z += a[2][q].z; a[0][q].w += a[2][q].w;
        a[1][q].x += a[3][q].x; a[1][q].y += a[3][q].y; a[1][q].z += a[3][q].z; a[1][q].w += a[3][q].w;
        a[0][q].x += a[1][q].x; a[0][q].y += a[1][q].y; a[0][q].z += a[1][q].z; a[0][q].w += a[1][q].w;
    }

    const int   cnt = s1 - s0;
    const float rc  = cnt ? (1.0f / (float)cnt) : 0.0f;   // max(cnt,1) semantics
    float m[8] = { a[0][0].x * rc, a[0][0].y * rc, a[0][0].z * rc, a[0][0].w * rc,
                   a[0][1].x * rc, a[0][1].y * rc, a[0][1].z * rc, a[0][1].w * rc };
    float h[8], l[8];
#pragma unroll
    for (int i = 0; i < 8; ++i) bsplit(m[i], h[i], l[i]);

    const size_t base = (size_t)(b * P_ + p) * K2_ + kq * 4;
    uint4 vh, vl;
    vh.x = bf16pack(h[0], h[1]); vh.y = bf16pack(h[2], h[3]);
    vh.z = bf16pack(h[4], h[5]); vh.w = bf16pack(h[6], h[7]);
    vl.x = bf16pack(l[0], l[1]); vl.y = bf16pack(l[2], l[3]);
    vl.z = bf16pack(l[4], l[5]); vl.w = bf16pack(l[6], l[7]);
    *reinterpret_cast<uint4*>(g_Ah + base) = vh;
    *reinterpret_cast<uint4*>(g_Al + base) = vl;
}

// ---------------------------------------------------------------------------
// Kernel 2: out = A @ W + bias, bf16 3-product split, everything pre-packed.
// M=1024, K=512, N=768. Block 64x96, BK=64 (8 iters), 512 threads (16 warps
// 4m x 4n, warp tile 16x24). cp.async 16B loads, 2-stage double buffer.
// grid = (8, 16) = 128 CTAs, single wave.
// ---------------------------------------------------------------------------
#define BM 64
#define BN 96
#define BK 64
#define BK2 (BK / 2)     // 32 packed words

// smem word-offset layout (per buffer 11264 words = 45056 B)
#define BUFW  11264
#define AHOF  0
#define ALOF  2304      // 64 * 36
#define WHOF  4608      // + 64*36
#define WLOF  7936      // + 32*104
#define ASTR  36        // 32 + 4 pad
#define WSTR  104       // 96 + 8 pad

__device__ __forceinline__ uint32_t smem_u32(const void* p) {
    uint32_t a;
    asm("{ .reg .u64 t; cvta.to.shared.u64 t, %1; cvt.u32.u64 %0, t; }"
        : "=r"(a) : "l"(p));
    return a;
}

__device__ __forceinline__ void cp16(uint32_t saddr, const void* gaddr) {
    asm volatile("cp.async.cg.shared.global [%0], [%1], 16;"
                 :: "r"(saddr), "l"(gaddr));
}

__device__ __forceinline__ void mma_bf16(float* c, const uint32_t* a,
                                         uint32_t b0, uint32_t b1) {
    asm volatile(
        "mma.sync.aligned.m16n8k16.row.col.f32.bf16.bf16.f32 "
        "{%0,%1,%2,%3}, {%4,%5,%6,%7}, {%8,%9}, {%0,%1,%2,%3};"
        : "+f"(c[0]), "+f"(c[1]), "+f"(c[2]), "+f"(c[3])
        : "r"(a[0]), "r"(a[1]), "r"(a[2]), "r"(a[3]), "r"(b0), "r"(b1));
}

__global__ __launch_bounds__(512, 1)
void gemm_kernel(const float* __restrict__ bias, float* __restrict__ out) {
    extern __shared__ uint32_t smw[];
    const uint32_t sb = smem_u32(smw);

    const int t  = threadIdx.x;          // 0..511
    const int w  = t >> 5;
    const int ln = t & 31;
    const int g  = ln >> 2;
    const int tg = ln & 3;
    const int wm = w & 3;                // 16-row slice
    const int wn = w >> 2;               // 24-col slice
    const int m0 = blockIdx.y * BM;
    const int n0 = blockIdx.x * BN;

    // loader indices
    const int ar = t >> 3;               // A row 0..63
    const int aj = (t & 3) ? (t & 7) : (t & 7);   // 16B unit 0..7
    const int aju = t & 7;
    const int wi1 = t;                   // W u4 index (768 per plane)
    const int wi2 = t + 512;             // second (only t<256)

    float acc[3][4] = {};

    // ---- pipelined loads
    auto load_chunk = [&](int c) {
        const int kb2 = c * BK2;
        // A: 64 rows x 8 u4 per plane
        {
            const uint32_t so = (ar * ASTR + aju * 4) * 4;
            const size_t  go = (size_t)(m0 + ar) * K2_ + kb2 + aju * 4;
            cp16(sb + ((c & 1) * BUFW + AHOF) * 4 + so, g_Ah + go);
            cp16(sb + ((c & 1) * BUFW + ALOF) * 4 + so, g_Al + go);
        }
        // W: 32 rows x 24 u4 per plane (768 u4)
        {
            const int r = wi1 / 24, cb = wi1 % 24;
            const uint32_t so = (r * WSTR + cb * 4) * 4;
            const size_t  go = (size_t)(kb2 + r) * D_ + n0 + cb * 4;
            cp16(sb + ((c & 1) * BUFW + WHOF) * 4 + so, g_Wh + go);
            cp16(sb + ((c & 1) * BUFW + WLOF) * 4 + so, g_Wl + go);
        }
        if (t < 256) {
            const int r = wi2 / 24, cb = wi2 % 24;
            const uint32_t so = (r * WSTR + cb * 4) * 4;
            const size_t  go = (size_t)(kb2 + r) * D_ + n0 + cb * 4;
            cp16(sb + ((c & 1) * BUFW + WHOF) * 4 + so, g_Wh + go);
            cp16(sb + ((c & 1) * BUFW + WLOF) * 4 + so, g_Wl + go);
        }
    };

    load_chunk(0);
    asm volatile("cp.async.commit_group;" ::: "memory");

    const int NCH = H_ / BK;             // 8
    for (int c = 0; c < NCH; ++c) {
        if (c + 1 < NCH) {
            load_chunk(c + 1);
            asm volatile("cp.async.commit_group;" ::: "memory");
            asm volatile("cp.async.wait_group 1;" ::: "memory");
        } else {
            asm volatile("cp.async.wait_group 0;" ::: "memory");
        }
        __syncthreads();

        const uint32_t* Ah = smw + (c & 1) * BUFW + AHOF;
        const uint32_t* Al = smw + (c & 1) * BUFW + ALOF;
        const uint32_t* Wh = smw + (c & 1) * BUFW + WHOF;
        const uint32_t* Wl = smw + (c & 1) * BUFW + WLOF;
        const int r = wm * 16 + g;

#pragma unroll
        for (int sl = 0; sl < 4; ++sl) {     // 4 k16-slabs per chunk
            const int cc = sl * 8 + tg;
            uint32_t ah[4], al[4];
            ah[0] = Ah[r * ASTR + cc];           al[0] = Al[r * ASTR + cc];
            ah[1] = Ah[(r + 8) * ASTR + cc];     al[1] = Al[(r + 8) * ASTR + cc];
            ah[2] = Ah[r * ASTR + cc + 4];       al[2] = Al[r * ASTR + cc + 4];
            ah[3] = Ah[(r + 8) * ASTR + cc + 4]; al[3] = Al[(r + 8) * ASTR + cc + 4];
#pragma unroll
            for (int nf = 0; nf < 3; ++nf) {
                const int n = wn * 24 + nf * 8 + g;
                const uint32_t bh0 = Wh[cc * WSTR + n];
                const uint32_t bh1 = Wh[(cc + 4) * WSTR + n];
                const uint32_t bl0 = Wl[cc * WSTR + n];
                const uint32_t bl1 = Wl[(cc + 4) * WSTR + n];
                mma_bf16(acc[nf], ah, bh0, bh1);   // hi*hi
                mma_bf16(acc[nf], al, bh0, bh1);   // lo*hi
                mma_bf16(acc[nf], ah, bl0, bl1);   // hi*lo
            }
        }
        __syncthreads();                 // buffer may be overwritten next iter
    }

    // ---- epilogue: c0,c1 = row g cols 2tg,2tg+1 ; c2,c3 = row g+8
#pragma unroll
    for (int nf = 0; nf < 3; ++nf) {
        const int ncol = n0 + wn * 24 + nf * 8 + 2 * tg;
        const float2 bv = *(const float2*)(bias + ncol);
        const int mrow = m0 + wm * 16 + g;
        float2 o0, o1;
        o0.x = acc[nf][0] + bv.x;  o0.y = acc[nf][1] + bv.y;
        o1.x = acc[nf][2] + bv.x;  o1.y = acc[nf][3] + bv.y;
        *(float2*)(out + (size_t)mrow * D_ + ncol)       = o0;
        *(float2*)(out + (size_t)(mrow + 8) * D_ + ncol) = o1;
    }
}

// ---------------------------------------------------------------------------
// Launch
// ---------------------------------------------------------------------------
extern "C" void kernel_launch(void* const* d_in, const int* in_sizes, int n_in,
                              void* d_out, int out_size) {
    const float* x    = (const float*)d_in[0];   // byte_hiddens [B,S,H]
    const float* W    = (const float*)d_in[1];   // W_proj [H,D]
    const float* bias = (const float*)d_in[2];   // b_proj [D]
    const int*   pids = (const int*)  d_in[3];   // patch_ids [B,S]
    float*       out  = (float*)d_out;           // [B,P,D]

    const int smem_bytes = 2 * BUFW * 4;         // 90112
    cudaFuncSetAttribute(gemm_kernel, cudaFuncAttributeMaxDynamicSharedMemorySize,
                         smem_bytes);

    pool_kernel<<<dim3(P_, B_, 2), 32>>>(x, W, pids);
    gemm_kernel<<<dim3(D_ / BN, M_ / BM), 512, smem_bytes>>>(bias, out);
}